// round 6
// baseline (speedup 1.0000x reference)
#include <cuda_runtime.h>
#include <cuda_bf16.h>
#include <cstdint>

// Problem constants
#define NPTS   32768
#define DK     512
#define NC0    1024
#define NC1    512
#define NC2    256
#define NCODES 1792
#define CB1_OFF 1024
#define CB2_OFF 1536

// out layout: main_out | sub_out | loss | ms_k_i(16x512 zeros) | unique
#define MAIN_OFF 0
#define SUB_OFF  (NPTS*DK)
#define LOSS_OFF (2*NPTS*DK)
#define MS_OFF   (LOSS_OFF + 1)
#define MS_N     (16*DK)
#define UNIQ_OFF (MS_OFF + MS_N)

#define MARGIN_BF 4.5f   // 2.0 hh-approx + ~2.4 bf16 quantization + safety

// Scratch (device globals; no allocation allowed)
__device__ float              g_cb[NCODES * DK];
__device__ float              g_halfnorm[NCODES];
__device__ unsigned long long g_amin[3 * NPTS];     // packed approx (fp32 score, idx)
__device__ float              g_loss[2];
__device__ int                g_used[NC0];
__device__ __nv_bfloat16      g_xh[NPTS * DK];
__device__ __nv_bfloat16      g_ch[NCODES * DK];
__device__ __nv_bfloat16      g_scb[(size_t)NPTS * NCODES];  // approx scores bf16 (112MB)

__device__ __forceinline__ unsigned int f2ord(float f) {
    unsigned int u = __float_as_uint(f);
    return (u & 0x80000000u) ? ~u : (u | 0x80000000u);
}
__device__ __forceinline__ float ord2f(unsigned int u) {
    unsigned int v = (u & 0x80000000u) ? (u & 0x7fffffffu) : ~u;
    return __uint_as_float(v);
}
__device__ __forceinline__ uint32_t smem_u32(const void* p) {
    uint32_t a;
    asm("{ .reg .u64 t; cvta.to.shared.u64 t, %1; cvt.u32.u64 %0, t; }" : "=r"(a) : "l"(p));
    return a;
}
__device__ __forceinline__ void cp16(uint32_t dst, const void* src) {
    asm volatile("cp.async.cg.shared.global [%0], [%1], 16;" :: "r"(dst), "l"(src));
}
#define CP_COMMIT() asm volatile("cp.async.commit_group;" ::: "memory")
#define CP_WAIT(n)  asm volatile("cp.async.wait_group %0;" :: "n"(n) : "memory")

__device__ __forceinline__ void ldsm4(uint32_t* r, uint32_t addr) {
    asm volatile("ldmatrix.sync.aligned.m8n8.x4.shared.b16 {%0,%1,%2,%3}, [%4];"
        : "=r"(r[0]), "=r"(r[1]), "=r"(r[2]), "=r"(r[3]) : "r"(addr));
}
__device__ __forceinline__ void mma_bf16(float* d, const uint32_t* a,
                                         uint32_t b0, uint32_t b1) {
    asm volatile("mma.sync.aligned.m16n8k16.row.col.f32.bf16.bf16.f32 "
        "{%0,%1,%2,%3}, {%4,%5,%6,%7}, {%8,%9}, {%0,%1,%2,%3};"
        : "+f"(d[0]), "+f"(d[1]), "+f"(d[2]), "+f"(d[3])
        : "r"(a[0]), "r"(a[1]), "r"(a[2]), "r"(a[3]), "r"(b0), "r"(b1));
}

// ---------------------------------------------------------------------------
// front: blocks [0,192) = sub-codebook GEMM (long-running, scheduled first);
//        blocks [192, 192+16384) = init + copy c + split x.      (launch #1)
// ---------------------------------------------------------------------------
__global__ __launch_bounds__(256) void k_front(
    const float* __restrict__ x, const float* __restrict__ c,
    const float* __restrict__ W1, const float* __restrict__ b1,
    const float* __restrict__ W2, const float* __restrict__ b2,
    float* __restrict__ out)
{
    if (blockIdx.x < 192) {
        // ---- sub codebooks ----
        const int bx = blockIdx.x;
        const int i0 = (bx % 96) * 8;
        const int d  = (bx / 96) * 256 + threadIdx.x;
        __shared__ float Ws[8][128];
        float acc[8];
#pragma unroll
        for (int r = 0; r < 8; r++) acc[r] = 0.0f;

        for (int j0 = 0; j0 < NC0; j0 += 128) {
#pragma unroll
            for (int l = 0; l < 4; l++) {
                int p = threadIdx.x + l * 256;
                int r = p >> 7, jj = p & 127;
                int gi = i0 + r;
                const float* Wrow = (gi < NC1) ? &W1[(size_t)gi * NC0]
                                               : &W2[(size_t)(gi - NC1) * NC0];
                Ws[r][jj] = Wrow[j0 + jj];
            }
            __syncthreads();
            for (int jj = 0; jj < 128; jj++) {
                float cv = c[(size_t)(j0 + jj) * DK + d];
#pragma unroll
                for (int r = 0; r < 8; r++) acc[r] += Ws[r][jj] * cv;
            }
            __syncthreads();
        }
#pragma unroll
        for (int r = 0; r < 8; r++) {
            int gi = i0 + r;
            float bias = (gi < NC1) ? b1[gi] : b2[gi - NC1];
            g_cb[(size_t)(CB1_OFF + gi) * DK + d] = acc[r] + bias;
        }
    } else {
        // ---- init + copy + split x ----
        int i = (blockIdx.x - 192) * 256 + threadIdx.x;
        if (i < NPTS * DK / 4) {
            float4 v = reinterpret_cast<const float4*>(x)[i];
            __nv_bfloat162* ph = reinterpret_cast<__nv_bfloat162*>(g_xh);
            ph[2*i]   = {__float2bfloat16(v.x), __float2bfloat16(v.y)};
            ph[2*i+1] = {__float2bfloat16(v.z), __float2bfloat16(v.w)};
        }
        if (i < NC0 * DK / 4)
            reinterpret_cast<float4*>(g_cb)[i] = reinterpret_cast<const float4*>(c)[i];
        if (i < 3 * NPTS) g_amin[i] = ~0ULL;
        if (i < MS_N)     out[MS_OFF + i] = 0.0f;
        if (i < NC0)      g_used[i] = 0;
        if (i < 2)        g_loss[i] = 0.0f;
    }
}

// ---------------------------------------------------------------------------
// prep2: split all codebooks to bf16 + halfnorms (one warp/row)  (launch #2)
// ---------------------------------------------------------------------------
__global__ __launch_bounds__(256) void k_prep2() {
    const int warp = (blockIdx.x * blockDim.x + threadIdx.x) >> 5;
    const int lane = threadIdx.x & 31;
    if (warp >= NCODES) return;
    const float4* row4 = reinterpret_cast<const float4*>(g_cb + (size_t)warp * DK);
    __nv_bfloat162* ch2 = reinterpret_cast<__nv_bfloat162*>(g_ch + (size_t)warp * DK);
    float s = 0.0f;
#pragma unroll
    for (int q = 0; q < 4; q++) {
        float4 v = row4[q * 32 + lane];
        s += v.x * v.x + v.y * v.y + v.z * v.z + v.w * v.w;
        ch2[(q * 32 + lane) * 2]     = {__float2bfloat16(v.x), __float2bfloat16(v.y)};
        ch2[(q * 32 + lane) * 2 + 1] = {__float2bfloat16(v.z), __float2bfloat16(v.w)};
    }
#pragma unroll
    for (int off = 16; off >= 1; off >>= 1) s += __shfl_xor_sync(0xffffffffu, s, off);
    if (lane == 0) g_halfnorm[warp] = 0.5f * s;
}

// ---------------------------------------------------------------------------
// HMMA approx GEMM (hh only, K=512) + approx argmin + bf16 score store.
// CTA tile 128x128, 8 warps (4m x 2n), BK=64, 3-stage cp.async.   (launch #3)
// ---------------------------------------------------------------------------
__device__ __forceinline__ void stage_chunk(int chunk, int stage, uint32_t sbase,
                                            int tid, int row0, int c0) {
    const int koff = chunk << 6;
    const uint32_t sA = sbase + (uint32_t)stage * 32768u;
    const uint32_t sB = sA + 16384u;
#pragma unroll
    for (int p = 0; p < 4; p++) {
        int idx = tid + (p << 8);
        int row = idx >> 3, cc = idx & 7;
        uint32_t sw = (uint32_t)((cc ^ (row & 7)) << 4);
        cp16(sA + (uint32_t)row * 128u + sw,
             g_xh + (size_t)(row0 + row) * DK + koff + cc * 8);
        cp16(sB + (uint32_t)row * 128u + sw,
             g_ch + (size_t)(c0 + row) * DK + koff + cc * 8);
    }
    CP_COMMIT();
}

__global__ __launch_bounds__(256) void k_mma() {
    extern __shared__ __align__(16) char smem[];
    __shared__ float hn_s[128];
    const uint32_t sbase = smem_u32(smem);
    const int tid  = threadIdx.x;
    const int lane = tid & 31;
    const int warp = tid >> 5;
    const int wm = warp >> 1;
    const int wn = warp & 1;
    const int c0   = blockIdx.x << 7;     // 14 code tiles
    const int row0 = blockIdx.y << 7;     // 256 row tiles

    if (tid < 128) hn_s[tid] = g_halfnorm[c0 + tid];

    float acc[2][8][4];
#pragma unroll
    for (int i = 0; i < 2; i++)
#pragma unroll
        for (int j = 0; j < 8; j++)
#pragma unroll
            for (int k = 0; k < 4; k++) acc[i][j][k] = 0.0f;

    stage_chunk(0, 0, sbase, tid, row0, c0);
    stage_chunk(1, 1, sbase, tid, row0, c0);

    const int rsel = lane & 15;
    const int ksel = lane >> 4;

    for (int chunk = 0; chunk < 8; chunk++) {
        const int stage = chunk % 3;
        if (chunk < 6) CP_WAIT(1); else CP_WAIT(0);
        __syncthreads();
        if (chunk + 2 < 8)
            stage_chunk(chunk + 2, (chunk + 2) % 3, sbase, tid, row0, c0);

        const uint32_t sA = sbase + (uint32_t)stage * 32768u;
        const uint32_t sB = sA + 16384u;
#pragma unroll
        for (int q = 0; q < 4; q++) {
            uint32_t a[2][4], b[4][4];
            const int csel = (q << 1) + ksel;
#pragma unroll
            for (int mf = 0; mf < 2; mf++) {
                int row = (wm << 5) + (mf << 4) + rsel;
                ldsm4(a[mf], sA + (uint32_t)row * 128u
                           + (uint32_t)((csel ^ (row & 7)) << 4));
            }
#pragma unroll
            for (int bt = 0; bt < 4; bt++) {
                int row = (wn << 6) + (bt << 4) + rsel;
                ldsm4(b[bt], sB + (uint32_t)row * 128u
                           + (uint32_t)((csel ^ (row & 7)) << 4));
            }
#pragma unroll
            for (int mf = 0; mf < 2; mf++)
#pragma unroll
                for (int bt = 0; bt < 4; bt++) {
                    mma_bf16(acc[mf][bt * 2],     a[mf], b[bt][0], b[bt][2]);
                    mma_bf16(acc[mf][bt * 2 + 1], a[mf], b[bt][1], b[bt][3]);
                }
        }
        __syncthreads();
    }

    // epilogue: approx score -> bf16 smem stage + register argmin (fp32 packed)
    const int grp = (blockIdx.x < 8) ? 0 : (blockIdx.x < 12) ? 1 : 2;
    const int g = lane >> 2, t = lane & 3;
    uint32_t* scs = reinterpret_cast<uint32_t*>(smem);   // [128][66] bf16x2 words

#pragma unroll
    for (int mf = 0; mf < 2; mf++) {
#pragma unroll
        for (int rh = 0; rh < 2; rh++) {
            const int row = (wm << 5) + (mf << 4) + (rh << 3) + g;
            unsigned long long best = ~0ULL;
#pragma unroll
            for (int nf = 0; nf < 8; nf++) {
                int colb = (wn << 6) + (nf << 3) + (t << 1);
                float s0 = hn_s[colb]     - acc[mf][nf][rh * 2];
                float s1 = hn_s[colb + 1] - acc[mf][nf][rh * 2 + 1];
                __nv_bfloat162 pb = {__float2bfloat16(s0), __float2bfloat16(s1)};
                scs[row * 66 + (colb >> 1)] = *reinterpret_cast<uint32_t*>(&pb);
                unsigned long long p0 = ((unsigned long long)f2ord(s0) << 32) | (unsigned)colb;
                unsigned long long p1 = ((unsigned long long)f2ord(s1) << 32) | (unsigned)(colb + 1);
                if (p0 < best) best = p0;
                if (p1 < best) best = p1;
            }
#pragma unroll
            for (int off = 2; off >= 1; off >>= 1) {
                unsigned long long q2 = __shfl_xor_sync(0xffffffffu, best, off);
                if (q2 < best) best = q2;
            }
            if (t == 0)
                atomicMin(&g_amin[(size_t)grp * NPTS + row0 + row], best);
        }
    }
    __syncthreads();

    // coalesced copy smem -> g_scb (256B per row)
    uint32_t* gsc32 = reinterpret_cast<uint32_t*>(g_scb);
#pragma unroll
    for (int r8 = 0; r8 < 128; r8 += 8) {
        int row = r8 + (tid >> 5);
        size_t rb = ((size_t)(row0 + row) * NCODES + c0) >> 1;
        gsc32[rb + lane]      = scs[row * 66 + lane];
        gsc32[rb + 32 + lane] = scs[row * 66 + 32 + lane];
    }
}

// ---------------------------------------------------------------------------
// fused exact-rescore + gather: one block (128 thr) per row.     (launch #4)
// ---------------------------------------------------------------------------
template<int NI>
__device__ __forceinline__ uint32_t scan_mask(const uint32_t* p, int lane, float thr) {
    uint32_t v[NI];
#pragma unroll
    for (int j = 0; j < NI; j++) v[j] = p[j * 32 + lane];
    uint32_t m = 0;
#pragma unroll
    for (int j = 0; j < NI; j++) {
        __nv_bfloat162 b2 = *reinterpret_cast<__nv_bfloat162*>(&v[j]);
        if (__bfloat162float(b2.x) <= thr) m |= 1u << (2 * j);
        if (__bfloat162float(b2.y) <= thr) m |= 1u << (2 * j + 1);
    }
    return m;
}

__global__ __launch_bounds__(128) void k_rg(const float* __restrict__ x,
                                            float* __restrict__ out) {
    const int row = blockIdx.x;
    const int tid = threadIdx.x;
    const int lane = tid & 31;
    const int w = tid >> 5;

    __shared__ float xs[DK];
    __shared__ int zres_s[3];

    reinterpret_cast<float4*>(xs)[tid] =
        reinterpret_cast<const float4*>(x + (size_t)row * DK)[tid];
    __syncthreads();

    if (w < 3) {
        const int gbase = (w == 0) ? 0 : (w == 1) ? CB1_OFF : CB2_OFF;
        const float thr =
            ord2f((unsigned)(g_amin[(size_t)w * NPTS + row] >> 32)) + MARGIN_BF;
        const uint32_t* p = reinterpret_cast<const uint32_t*>(g_scb)
                          + (((size_t)row * NCODES + gbase) >> 1);
        uint32_t msk = (w == 0) ? scan_mask<16>(p, lane, thr)
                     : (w == 1) ? scan_mask<8>(p, lane, thr)
                                : scan_mask<4>(p, lane, thr);
        const float4* xs4 = reinterpret_cast<const float4*>(xs);
        double bs = 1e300;
        int bi = 0;
        unsigned lanes = __ballot_sync(0xffffffffu, msk != 0);
        while (lanes) {
            int L = __ffs(lanes) - 1;
            lanes &= lanes - 1;
            uint32_t lm = __shfl_sync(0xffffffffu, msk, L);
            while (lm) {
                int b = __ffs(lm) - 1;
                lm &= lm - 1;
                int li = ((b >> 1) << 6) + (L << 1) + (b & 1);
                const float4* cr4 = reinterpret_cast<const float4*>(
                    g_cb + (size_t)(gbase + li) * DK);
                double ds = 0.0;
#pragma unroll
                for (int q = 0; q < 4; q++) {
                    float4 xv = xs4[q * 32 + lane];
                    float4 cv = cr4[q * 32 + lane];
                    ds = fma((double)xv.x, (double)cv.x, ds);
                    ds = fma((double)xv.y, (double)cv.y, ds);
                    ds = fma((double)xv.z, (double)cv.z, ds);
                    ds = fma((double)xv.w, (double)cv.w, ds);
                }
#pragma unroll
                for (int off = 16; off >= 1; off >>= 1)
                    ds += __shfl_xor_sync(0xffffffffu, ds, off);
                double sc = (double)g_halfnorm[gbase + li] - ds;
                if (sc < bs) { bs = sc; bi = li; }
            }
        }
        if (lane == 0) zres_s[w] = bi;
    }
    __syncthreads();

    const int z  = zres_s[0];
    const int z1 = zres_s[1];
    const int z2 = zres_s[2];
    if (tid == 0) g_used[z] = 1;

    const float4* m  = reinterpret_cast<const float4*>(&g_cb[(size_t)z * DK]);
    const float4* s1 = reinterpret_cast<const float4*>(&g_cb[(size_t)(CB1_OFF + z1) * DK]);
    const float4* s2 = reinterpret_cast<const float4*>(&g_cb[(size_t)(CB2_OFF + z2) * DK]);
    float4* om = reinterpret_cast<float4*>(&out[MAIN_OFF + (size_t)row * DK]);
    float4* os = reinterpret_cast<float4*>(&out[SUB_OFF + (size_t)row * DK]);

    float4 xv = reinterpret_cast<const float4*>(xs)[tid];
    float4 mv = m[tid];
    float4 a  = s1[tid];
    float4 b  = s2[tid];
    float4 sv = make_float4(0.5f * (a.x + b.x), 0.5f * (a.y + b.y),
                            0.5f * (a.z + b.z), 0.5f * (a.w + b.w));
    om[tid] = mv;
    os[tid] = sv;

    float dmx = mv.x - xv.x, dmy = mv.y - xv.y, dmz = mv.z - xv.z, dmw = mv.w - xv.w;
    float dsx = sv.x - xv.x, dsy = sv.y - xv.y, dsz = sv.z - xv.z, dsw = sv.w - xv.w;
    float lm = dmx * dmx + dmy * dmy + dmz * dmz + dmw * dmw;
    float ls = dsx * dsx + dsy * dsy + dsz * dsz + dsw * dsw;

#pragma unroll
    for (int off = 16; off >= 1; off >>= 1) {
        lm += __shfl_xor_sync(0xffffffffu, lm, off);
        ls += __shfl_xor_sync(0xffffffffu, ls, off);
    }
    __shared__ float sm[4], ss[4];
    if (lane == 0) { sm[w] = lm; ss[w] = ls; }
    __syncthreads();
    if (tid == 0) {
        atomicAdd(&g_loss[0], sm[0] + sm[1] + sm[2] + sm[3]);
        atomicAdd(&g_loss[1], ss[0] + ss[1] + ss[2] + ss[3]);
    }
}

// ---------------------------------------------------------------------------
__global__ void k_final(const int* __restrict__ training, float* __restrict__ out) {
    const int tid = threadIdx.x;
    int cnt = 0;
    for (int i = tid; i < NC0; i += 256) cnt += g_used[i];
#pragma unroll
    for (int off = 16; off >= 1; off >>= 1) cnt += __shfl_xor_sync(0xffffffffu, cnt, off);
    __shared__ int sc[8];
    int wid = tid >> 5, lane = tid & 31;
    if (lane == 0) sc[wid] = cnt;
    __syncthreads();
    if (tid == 0) {
        int total = 0;
#pragma unroll
        for (int w = 0; w < 8; w++) total += sc[w];
        float e_sum = g_loss[0] + g_loss[1];
        out[LOSS_OFF] = (*training != 0)
                      ? 1.25f * e_sum / ((float)NPTS * (float)DK) : 0.0f;
        out[UNIQ_OFF] = (float)total;
    }
}

// ---------------------------------------------------------------------------
extern "C" void kernel_launch(void* const* d_in, const int* in_sizes, int n_in,
                              void* d_out, int out_size) {
    const float* x  = (const float*)d_in[0];
    const float* c  = (const float*)d_in[1];
    const float* W1 = (const float*)d_in[2];
    const float* b1 = (const float*)d_in[3];
    const float* W2 = (const float*)d_in[4];
    const float* b2 = (const float*)d_in[5];
    const int* training = (const int*)d_in[6];
    float* out = (float*)d_out;

    const int MMA_SMEM = 3 * 32768;   // 96KB (>= 128*66*4 epilogue staging)
    cudaFuncSetAttribute(k_mma, cudaFuncAttributeMaxDynamicSharedMemorySize, MMA_SMEM);

    k_front<<<192 + 16384, 256>>>(x, c, W1, b1, W2, b2, out);       // #1
    k_prep2<<<(NCODES * 32 + 255) / 256, 256>>>();                   // #2
    {
        dim3 g(NCODES / 128, NPTS / 128);   // (14, 256)
        k_mma<<<g, 256, MMA_SMEM>>>();                               // #3
    }
    k_rg<<<NPTS, 128>>>(x, out);                                     // #4
    k_final<<<1, 256>>>(training, out);                              // #5
}